// round 11
// baseline (speedup 1.0000x reference)
#include <cuda_runtime.h>
#include <cuda_bf16.h>
#include <math.h>
#include <stdint.h>

#define Bz 8
#define Tt 1024
#define Ss 1024
#define Dm 512
#define Hh 8
#define DKh 64
#define FFd 2048
#define NL 6

// ---------------- scratch (device globals) ----------------
__device__ __align__(256) float g_x  [Bz*Tt*Dm];
__device__ __align__(256) float g_t  [Bz*Tt*Dm];

__device__ __align__(256) __nv_bfloat16 g_xhi[Bz*Tt*Dm];
__device__ __align__(256) __nv_bfloat16 g_xlo[Bz*Tt*Dm];
__device__ __align__(256) __nv_bfloat16 g_qkvhi[Bz*Tt*1536];
__device__ __align__(256) __nv_bfloat16 g_qkvlo[Bz*Tt*1536];
__device__ __align__(256) __nv_bfloat16 g_chi[Bz*Tt*Dm];
__device__ __align__(256) __nv_bfloat16 g_clo[Bz*Tt*Dm];
__device__ __align__(256) __nv_bfloat16 g_hhi[Bz*Tt*FFd];
__device__ __align__(256) __nv_bfloat16 g_hlo[Bz*Tt*FFd];
__device__ __align__(256) __nv_bfloat16 g_ehi[Bz*Ss*Dm];
__device__ __align__(256) __nv_bfloat16 g_elo[Bz*Ss*Dm];

#define WT_L 4194304
__device__ __align__(256) __nv_bfloat16 g_wthi[(size_t)NL*WT_L];
__device__ __align__(256) __nv_bfloat16 g_wtlo[(size_t)NL*WT_L];
__device__ __align__(256) __nv_bfloat16 g_vthi[Bz*Hh*DKh*Ss];
__device__ __align__(256) __nv_bfloat16 g_vtlo[Bz*Hh*DKh*Ss];

// ---------------- helpers ----------------
__device__ __forceinline__ uint32_t smem_u32(const void* p) {
    uint32_t a;
    asm("{ .reg .u64 t; cvta.to.shared.u64 t, %1; cvt.u32.u64 %0, t; }" : "=r"(a) : "l"(p));
    return a;
}
__device__ __forceinline__ void cpa16(uint32_t s, const void* g) {
    asm volatile("cp.async.ca.shared.global [%0], [%1], 16;" :: "r"(s), "l"(g));
}
#define CP_COMMIT() asm volatile("cp.async.commit_group;" ::: "memory")
#define CP_WAIT1()  asm volatile("cp.async.wait_group 1;" ::: "memory")
#define CP_WAIT0()  asm volatile("cp.async.wait_group 0;" ::: "memory")

__device__ __forceinline__ void ldm4(uint32_t* r, uint32_t addr) {
    asm volatile("ldmatrix.sync.aligned.m8n8.x4.shared.b16 {%0,%1,%2,%3}, [%4];"
        : "=r"(r[0]), "=r"(r[1]), "=r"(r[2]), "=r"(r[3]) : "r"(addr));
}
__device__ __forceinline__ void mma16816(float* c, const uint32_t* a, const uint32_t* b) {
    asm volatile("mma.sync.aligned.m16n8k16.row.col.f32.bf16.bf16.f32 "
        "{%0,%1,%2,%3}, {%4,%5,%6,%7}, {%8,%9}, {%0,%1,%2,%3};"
        : "+f"(c[0]), "+f"(c[1]), "+f"(c[2]), "+f"(c[3])
        : "r"(a[0]), "r"(a[1]), "r"(a[2]), "r"(a[3]), "r"(b[0]), "r"(b[1]));
}
__device__ __forceinline__ void split_store(float a, float b,
                                            __nv_bfloat16* hi, __nv_bfloat16* lo) {
    __nv_bfloat16 ha = __float2bfloat16(a), hb = __float2bfloat16(b);
    __nv_bfloat162 H; H.x = ha; H.y = hb;
    __nv_bfloat162 L;
    L.x = __float2bfloat16(a - __bfloat162float(ha));
    L.y = __float2bfloat16(b - __bfloat162float(hb));
    *(__nv_bfloat162*)hi = H;
    *(__nv_bfloat162*)lo = L;
}
__device__ __forceinline__ void split_pack(float a, float b, uint32_t& H, uint32_t& L) {
    __nv_bfloat16 ha = __float2bfloat16(a), hb = __float2bfloat16(b);
    __nv_bfloat162 Hv; Hv.x = ha; Hv.y = hb;
    __nv_bfloat162 Lv;
    Lv.x = __float2bfloat16(a - __bfloat162float(ha));
    Lv.y = __float2bfloat16(b - __bfloat162float(hb));
    H = *reinterpret_cast<uint32_t*>(&Hv);
    L = *reinterpret_cast<uint32_t*>(&Lv);
}

// ================= pipelined warp-MMA GEMM (bf16x3, TILE 128x64, 2 CTA/SM) =================
// D[M,N] = A[M,K] * B^T, pre-split hi/lo bf16. EPI: 0 plain, 1 relu.
#define GPITCH 72
#define GSTAGE ((256 + 128) * GPITCH * 2)   // 55296
#define GSMEM  (2 * GSTAGE)                 // 110592 -> 2 CTAs/SM

template<int EPI>
__global__ void __launch_bounds__(256) mm2(
    const __nv_bfloat16* __restrict__ Ah, const __nv_bfloat16* __restrict__ Al, int lda,
    const __nv_bfloat16* __restrict__ Bh, const __nv_bfloat16* __restrict__ Bl, int ldb,
    float* __restrict__ Cf, __nv_bfloat16* __restrict__ Chi, __nv_bfloat16* __restrict__ Clo,
    int ldc, int K)
{
    extern __shared__ char smem[];
    uint32_t sb = smem_u32(smem);

    int tid = threadIdx.x, warp = tid >> 5, lane = tid & 31;
    int m0 = blockIdx.y * 128, n0 = blockIdx.x * 64;
    int wm = warp & 3, wn = warp >> 2;            // 4x2 warp grid
    int mbase = wm * 32, nbase = wn * 32;

    float acc[2][4][4];
#pragma unroll
    for (int i = 0; i < 2; i++)
#pragma unroll
        for (int j = 0; j < 4; j++)
#pragma unroll
            for (int c = 0; c < 4; c++) acc[i][j][c] = 0.0f;

    const int a_row = (lane & 15), a_koff = ((lane >> 4) << 3);
    const int b_row = ((lane >> 4) << 3) + (lane & 7), b_koff = (((lane >> 3) & 1) << 3);

    auto issue = [&](int stage, int k0) {
        uint32_t base = sb + stage * GSTAGE;
        uint32_t uAh = base, uAl = base + 128 * GPITCH * 2;
        uint32_t uBh = base + 256 * GPITCH * 2, uBl = uBh + 64 * GPITCH * 2;
#pragma unroll
        for (int i = 0; i < 4; i++) {
            int idx = tid + 256 * i;
            int r = idx >> 3, c = idx & 7;
            long g = (long)(m0 + r) * lda + k0 + c * 8;
            uint32_t so = (uint32_t)(r * GPITCH + c * 8) * 2;
            cpa16(uAh + so, Ah + g);
            cpa16(uAl + so, Al + g);
        }
#pragma unroll
        for (int i = 0; i < 2; i++) {
            int idx = tid + 256 * i;
            int r = idx >> 3, c = idx & 7;
            long g = (long)(n0 + r) * ldb + k0 + c * 8;
            uint32_t so = (uint32_t)(r * GPITCH + c * 8) * 2;
            cpa16(uBh + so, Bh + g);
            cpa16(uBl + so, Bl + g);
        }
        CP_COMMIT();
    };

    int nch = K >> 6;
    issue(0, 0);
    if (nch > 1) issue(1, 64);

    for (int it = 0; it < nch; it++) {
        if (it + 2 <= nch) CP_WAIT1(); else CP_WAIT0();
        __syncthreads();
        uint32_t base = sb + (it & 1) * GSTAGE;
        uint32_t uAh = base, uAl = base + 128 * GPITCH * 2;
        uint32_t uBh = base + 256 * GPITCH * 2, uBl = uBh + 64 * GPITCH * 2;

#pragma unroll
        for (int ks = 0; ks < 4; ks++) {
            uint32_t ah[2][4], al[2][4];
#pragma unroll
            for (int mi = 0; mi < 2; mi++) {
                uint32_t ro = (uint32_t)((mbase + mi * 16 + a_row) * GPITCH + ks * 16 + a_koff) * 2;
                ldm4(ah[mi], uAh + ro);
                ldm4(al[mi], uAl + ro);
            }
            uint32_t bh[4][2], bl[4][2];
#pragma unroll
            for (int nj = 0; nj < 2; nj++) {
                uint32_t ro = (uint32_t)((nbase + nj * 16 + b_row) * GPITCH + ks * 16 + b_koff) * 2;
                uint32_t t4[4];
                ldm4(t4, uBh + ro);
                bh[2 * nj][0] = t4[0]; bh[2 * nj][1] = t4[1];
                bh[2 * nj + 1][0] = t4[2]; bh[2 * nj + 1][1] = t4[3];
                ldm4(t4, uBl + ro);
                bl[2 * nj][0] = t4[0]; bl[2 * nj][1] = t4[1];
                bl[2 * nj + 1][0] = t4[2]; bl[2 * nj + 1][1] = t4[3];
            }
#pragma unroll
            for (int mi = 0; mi < 2; mi++)
#pragma unroll
                for (int ni = 0; ni < 4; ni++) {
                    mma16816(acc[mi][ni], ah[mi], bh[ni]);
                    mma16816(acc[mi][ni], ah[mi], bl[ni]);
                    mma16816(acc[mi][ni], al[mi], bh[ni]);
                }
        }
        __syncthreads();
        if (it + 2 < nch) issue(it & 1, (it + 2) * 64);
    }

#pragma unroll
    for (int mi = 0; mi < 2; mi++) {
#pragma unroll
        for (int ni = 0; ni < 4; ni++) {
            int m = m0 + mbase + mi * 16 + (lane >> 2);
            int n = n0 + nbase + ni * 8 + (lane & 3) * 2;
            float* c0 = acc[mi][ni];
            float a0 = c0[0], a1 = c0[1], a2 = c0[2], a3 = c0[3];
            if (EPI == 1) {
                a0 = fmaxf(a0, 0.f); a1 = fmaxf(a1, 0.f);
                a2 = fmaxf(a2, 0.f); a3 = fmaxf(a3, 0.f);
            }
            if (Cf) {
                *(float2*)(Cf + (long)m * ldc + n) = make_float2(a0, a1);
                *(float2*)(Cf + (long)(m + 8) * ldc + n) = make_float2(a2, a3);
            }
            if (Chi) {
                split_store(a0, a1, Chi + (long)m * ldc + n, Clo + (long)m * ldc + n);
                split_store(a2, a3, Chi + (long)(m + 8) * ldc + n, Clo + (long)(m + 8) * ldc + n);
            }
        }
    }
}

// ================= fused flash attention (bf16x3, online softmax) =================
#define KPITCH 72
#define VPITCH 136
#define FL_STAGE 71680
#define FL_SMEM  (2 * FL_STAGE + 512)

template<int CAUSAL>
__global__ void __launch_bounds__(256) flash(
    const __nv_bfloat16* __restrict__ Qh, const __nv_bfloat16* __restrict__ Ql, int ldq,
    const __nv_bfloat16* __restrict__ Kh, const __nv_bfloat16* __restrict__ Kl,
    const __nv_bfloat16* __restrict__ Vth, const __nv_bfloat16* __restrict__ Vtl,
    __nv_bfloat16* __restrict__ Chi, __nv_bfloat16* __restrict__ Clo,
    const int* __restrict__ tok)
{
    extern __shared__ char smem[];
    uint32_t sb = smem_u32(smem);
    float* msk = (float*)(smem + 2 * FL_STAGE);

    int tid = threadIdx.x, warp = tid >> 5, lane = tid & 31;
    int z = blockIdx.y, b = z >> 3, h = z & 7;
    int q0 = blockIdx.x * 128;
    int mbase = warp * 16;

    const __nv_bfloat16* Qhb = Qh + ((long)(b * Tt + q0)) * ldq + h * 64;
    const __nv_bfloat16* Qlb = Ql + ((long)(b * Tt + q0)) * ldq + h * 64;
    const __nv_bfloat16* Khb = Kh + ((long)b * Ss) * ldq + h * 64;
    const __nv_bfloat16* Klb = Kl + ((long)b * Ss) * ldq + h * 64;
    const __nv_bfloat16* Vhb = Vth + (long)z * 64 * Ss;
    const __nv_bfloat16* Vlb = Vtl + (long)z * 64 * Ss;
    const int* tokb = tok + b * 1024;

    const int a_row = (lane & 15), a_koff = ((lane >> 4) << 3);
    const int b_row = ((lane >> 4) << 3) + (lane & 7), b_koff = (((lane >> 3) & 1) << 3);

    {
        uint32_t uQh = sb, uQl = sb + 128 * KPITCH * 2;
#pragma unroll
        for (int i = 0; i < 4; i++) {
            int idx = tid + 256 * i;
            int r = idx >> 3, c = idx & 7;
            long g = (long)r * ldq + c * 8;
            uint32_t so = (uint32_t)(r * KPITCH + c * 8) * 2;
            cpa16(uQh + so, Qhb + g);
            cpa16(uQl + so, Qlb + g);
        }
        CP_COMMIT(); CP_WAIT0();
        __syncthreads();
    }
    uint32_t qh[4][4], ql[4][4];
#pragma unroll
    for (int ks = 0; ks < 4; ks++) {
        ldm4(qh[ks], sb + (uint32_t)((mbase + a_row) * KPITCH + ks * 16 + a_koff) * 2);
        ldm4(ql[ks], sb + 128 * KPITCH * 2 + (uint32_t)((mbase + a_row) * KPITCH + ks * 16 + a_koff) * 2);
    }
    __syncthreads();

    auto issue = [&](int stage, int kb) {
        uint32_t base = sb + stage * FL_STAGE;
        uint32_t uKhi = base, uKlo = base + 18432;
        uint32_t uVhi = base + 36864, uVlo = base + 54272;
#pragma unroll
        for (int i = 0; i < 4; i++) {
            int idx = tid + 256 * i;
            int r = idx >> 3, c = idx & 7;
            long g = (long)(kb * 128 + r) * ldq + c * 8;
            uint32_t so = (uint32_t)(r * KPITCH + c * 8) * 2;
            cpa16(uKhi + so, Khb + g);
            cpa16(uKlo + so, Klb + g);
        }
#pragma unroll
        for (int i = 0; i < 4; i++) {
            int idx = tid + 256 * i;
            int r = idx >> 4, c = idx & 15;
            long g = (long)r * Ss + kb * 128 + c * 8;
            uint32_t so = (uint32_t)(r * VPITCH + c * 8) * 2;
            cpa16(uVhi + so, Vhb + g);
            cpa16(uVlo + so, Vlb + g);
        }
        CP_COMMIT();
    };

    const float CSC = 0.125f * 1.4426950408889634f;
    float oacc[8][4];
#pragma unroll
    for (int i = 0; i < 8; i++)
#pragma unroll
        for (int c = 0; c < 4; c++) oacc[i][c] = 0.0f;
    float m0 = -INFINITY, m1 = -INFINITY, l0 = 0.0f, l1 = 0.0f;
    const int qr0 = q0 + mbase + (lane >> 2);
    const int qr1 = qr0 + 8;

    int nkb = CAUSAL ? (q0 / 128 + 1) : (Ss / 128);
    issue(0, 0);
    if (nkb > 1) issue(1, 1);

    for (int kb = 0; kb < nkb; kb++) {
        int tokv = 0;
        if (tid < 128) tokv = tokb[kb * 128 + tid];
        if (kb + 2 <= nkb) CP_WAIT1(); else CP_WAIT0();
        __syncthreads();
        if (tid < 128) msk[tid] = (tokv == 0) ? 1.0f : 0.0f;
        __syncthreads();

        uint32_t base = sb + (kb & 1) * FL_STAGE;
        uint32_t uK[2] = { base, base + 18432 };
        uint32_t uV[2] = { base + 36864, base + 54272 };

        float sacc[16][4];
#pragma unroll
        for (int i = 0; i < 16; i++)
#pragma unroll
            for (int c = 0; c < 4; c++) sacc[i][c] = 0.0f;
#pragma unroll
        for (int pass = 0; pass < 3; pass++) {
            uint32_t (*qr)[4] = (pass == 2) ? ql : qh;
            uint32_t pK = uK[pass == 1];
#pragma unroll
            for (int ks = 0; ks < 4; ks++) {
#pragma unroll
                for (int nj = 0; nj < 8; nj++) {
                    uint32_t t4[4];
                    ldm4(t4, pK + (uint32_t)((nj * 16 + b_row) * KPITCH + ks * 16 + b_koff) * 2);
                    mma16816(sacc[2 * nj], qr[ks], t4);
                    mma16816(sacc[2 * nj + 1], qr[ks], t4 + 2);
                }
            }
        }

        float mx0 = -INFINITY, mx1 = -INFINITY;
#pragma unroll
        for (int t = 0; t < 16; t++) {
            int cb = t * 8 + (lane & 3) * 2;
            float2 mv = *(float2*)(msk + cb);
            int kg = kb * 128 + cb;
            bool M0 = (mv.x != 0.0f), M1 = (mv.y != 0.0f);
            bool c00 = M0 || (CAUSAL && kg > qr0);
            bool c01 = M1 || (CAUSAL && kg + 1 > qr0);
            bool c10 = M0 || (CAUSAL && kg > qr1);
            bool c11 = M1 || (CAUSAL && kg + 1 > qr1);
            sacc[t][0] = c00 ? -1e9f : sacc[t][0] * CSC;
            sacc[t][1] = c01 ? -1e9f : sacc[t][1] * CSC;
            sacc[t][2] = c10 ? -1e9f : sacc[t][2] * CSC;
            sacc[t][3] = c11 ? -1e9f : sacc[t][3] * CSC;
            mx0 = fmaxf(mx0, fmaxf(sacc[t][0], sacc[t][1]));
            mx1 = fmaxf(mx1, fmaxf(sacc[t][2], sacc[t][3]));
        }
        mx0 = fmaxf(mx0, __shfl_xor_sync(0xffffffffu, mx0, 1));
        mx0 = fmaxf(mx0, __shfl_xor_sync(0xffffffffu, mx0, 2));
        mx1 = fmaxf(mx1, __shfl_xor_sync(0xffffffffu, mx1, 1));
        mx1 = fmaxf(mx1, __shfl_xor_sync(0xffffffffu, mx1, 2));

        float m0n = fmaxf(m0, mx0), m1n = fmaxf(m1, mx1);
        float al0 = exp2f(m0 - m0n), al1 = exp2f(m1 - m1n);
        m0 = m0n; m1 = m1n;
        l0 *= al0; l1 *= al1;
#pragma unroll
        for (int i = 0; i < 8; i++) {
            oacc[i][0] *= al0; oacc[i][1] *= al0;
            oacc[i][2] *= al1; oacc[i][3] *= al1;
        }

        float ls0 = 0.0f, ls1 = 0.0f;
#pragma unroll
        for (int half = 0; half < 2; half++) {
            uint32_t ph[4][4], pl[4][4];
#pragma unroll
            for (int ksv = 0; ksv < 4; ksv++) {
                int tA = half * 8 + ksv * 2, tB = tA + 1;
                float p00 = exp2f(sacc[tA][0] - m0), p01 = exp2f(sacc[tA][1] - m0);
                float p02 = exp2f(sacc[tA][2] - m1), p03 = exp2f(sacc[tA][3] - m1);
                float p10 = exp2f(sacc[tB][0] - m0), p11 = exp2f(sacc[tB][1] - m0);
                float p12 = exp2f(sacc[tB][2] - m1), p13 = exp2f(sacc[tB][3] - m1);
                ls0 += p00 + p01 + p10 + p11;
                ls1 += p02 + p03 + p12 + p13;
                split_pack(p00, p01, ph[ksv][0], pl[ksv][0]);
                split_pack(p02, p03, ph[ksv][1], pl[ksv][1]);
                split_pack(p10, p11, ph[ksv][2], pl[ksv][2]);
                split_pack(p12, p13, ph[ksv][3], pl[ksv][3]);
            }
#pragma unroll
            for (int pass = 0; pass < 3; pass++) {
                uint32_t (*pa)[4] = (pass == 2) ? pl : ph;
                uint32_t pV = uV[pass == 1];
#pragma unroll
                for (int ksv = 0; ksv < 4; ksv++) {
                    int ksg = half * 4 + ksv;
#pragma unroll
                    for (int nj = 0; nj < 4; nj++) {
                        uint32_t t4[4];
                        ldm4(t4, pV + (uint32_t)((nj * 16 + b_row) * VPITCH + ksg * 16 + b_koff) * 2);
                        mma16816(oacc[2 * nj], pa[ksv], t4);
                        mma16816(oacc[2 * nj + 1], pa[ksv], t4 + 2);
                    }
                }
            }
        }
        ls0 += __shfl_xor_sync(0xffffffffu, ls0, 1);
        ls0 += __shfl_xor_sync(0xffffffffu, ls0, 2);
        ls1 += __shfl_xor_sync(0xffffffffu, ls1, 1);
        ls1 += __shfl_xor_sync(0xffffffffu, ls1, 2);
        l0 += ls0; l1 += ls1;

        __syncthreads();
        if (kb + 2 < nkb) issue(kb & 1, kb + 2);
    }

    float il0 = 1.0f / l0, il1 = 1.0f / l1;
    long gr0 = (long)(b * Tt + q0 + mbase + (lane >> 2));
    long gr1 = gr0 + 8;
#pragma unroll
    for (int oi = 0; oi < 8; oi++) {
        int col = h * 64 + oi * 8 + (lane & 3) * 2;
        split_store(oacc[oi][0] * il0, oacc[oi][1] * il0,
                    Chi + gr0 * Dm + col, Clo + gr0 * Dm + col);
        split_store(oacc[oi][2] * il1, oacc[oi][3] * il1,
                    Chi + gr1 * Dm + col, Clo + gr1 * Dm + col);
    }
}

// ---------------- weight transpose + split, batched over layers ----------------
__global__ void wt_build(const float* __restrict__ W, __nv_bfloat16* __restrict__ Whi,
                         __nv_bfloat16* __restrict__ Wlo, int Kd, int Nd,
                         long srcStride, long dstStride)
{
    int l = blockIdx.z;
    W += (long)l * srcStride; Whi += (long)l * dstStride; Wlo += (long)l * dstStride;
    __shared__ float t[32][33];
    int k0 = blockIdx.y * 32, n0 = blockIdx.x * 32;
    t[threadIdx.y][threadIdx.x] = W[(long)(k0 + threadIdx.y) * Nd + n0 + threadIdx.x];
    __syncthreads();
    float v = t[threadIdx.x][threadIdx.y];
    long o = (long)(n0 + threadIdx.y) * Kd + k0 + threadIdx.x;
    __nv_bfloat16 h = __float2bfloat16(v);
    Whi[o] = h;
    Wlo[o] = __float2bfloat16(v - __bfloat162float(h));
}

// ---------------- V transpose from split qkv buffer (bf16 in, bf16 out) ----------------
__global__ void vt_build(const __nv_bfloat16* __restrict__ qh, const __nv_bfloat16* __restrict__ qlo,
                         __nv_bfloat16* __restrict__ vhi, __nv_bfloat16* __restrict__ vlo)
{
    int z = blockIdx.z, b = z >> 3, h = z & 7;
    __shared__ __nv_bfloat16 th[32][34], tl[32][34];
    int s0 = blockIdx.x * 32, d0 = blockIdx.y * 32;
    long src = (long)(b * Ss + s0 + threadIdx.y) * 1536 + 1024 + h * 64 + d0 + threadIdx.x;
    th[threadIdx.y][threadIdx.x] = qh[src];
    tl[threadIdx.y][threadIdx.x] = qlo[src];
    __syncthreads();
    long o = (long)(z * 64 + d0 + threadIdx.y) * Ss + s0 + threadIdx.x;
    vhi[o] = th[threadIdx.x][threadIdx.y];
    vlo[o] = tl[threadIdx.x][threadIdx.y];
}

// ---------------- embedding + PE ----------------
__global__ void embed_k(const int* __restrict__ dec, const float* __restrict__ emb,
                        float* __restrict__ x, __nv_bfloat16* __restrict__ xhi,
                        __nv_bfloat16* __restrict__ xlo)
{
    int bt = blockIdx.x;
    int tpos = bt & (Tt - 1);
    int tokv = dec[bt];
    int d0 = threadIdx.x * 4;
    const double c0 = -9.210340371976184 / (double)Dm;
    float vals[4];
#pragma unroll
    for (int i = 0; i < 4; i++) {
        int d = d0 + i;
        int pair = d >> 1;
        double div = exp((double)(2 * pair) * c0);
        double ang = (double)tpos * div;
        float pe = (float)((d & 1) ? cos(ang) : sin(ang));
        float e = (tokv == 0) ? 0.0f : emb[(size_t)tokv * Dm + d];
        vals[i] = e + pe;
    }
    size_t o = (size_t)bt * Dm + d0;
    *(float4*)(x + o) = *(float4*)vals;
    split_store(vals[0], vals[1], xhi + o, xlo + o);
    split_store(vals[2], vals[3], xhi + o + 2, xlo + o + 2);
}

// ---------------- enc_out split ----------------
__global__ void enc_split(const float* __restrict__ e, __nv_bfloat16* __restrict__ ehi,
                          __nv_bfloat16* __restrict__ elo)
{
    size_t o = (size_t)blockIdx.x * Dm + threadIdx.x * 4;
    float4 v = *(const float4*)(e + o);
    split_store(v.x, v.y, ehi + o, elo + o);
    split_store(v.z, v.w, ehi + o + 2, elo + o + 2);
}

// ---------------- out = LayerNorm(a + b) ----------------
__global__ void add_ln_k(const float* __restrict__ A, const float* __restrict__ Bres,
                         float* __restrict__ O, __nv_bfloat16* __restrict__ Ohi,
                         __nv_bfloat16* __restrict__ Olo)
{
    size_t r = blockIdx.x;
    int t = threadIdx.x;
    size_t o = r * Dm + t * 4;
    float4 va = *(const float4*)(A + o);
    float4 vb = *(const float4*)(Bres + o);
    float v[4] = { va.x + vb.x, va.y + vb.y, va.z + vb.z, va.w + vb.w };
    float s = v[0] + v[1] + v[2] + v[3];
    __shared__ float red[128];
    red[t] = s; __syncthreads();
    for (int st = 64; st > 0; st >>= 1) { if (t < st) red[t] += red[t + st]; __syncthreads(); }
    float mu = red[0] * (1.0f / Dm);
    __syncthreads();
    float s2 = 0.0f;
#pragma unroll
    for (int i = 0; i < 4; i++) { float d = v[i] - mu; s2 += d * d; }
    red[t] = s2; __syncthreads();
    for (int st = 64; st > 0; st >>= 1) { if (t < st) red[t] += red[t + st]; __syncthreads(); }
    float inv = rsqrtf(red[0] * (1.0f / Dm) + 1e-5f);
    float out[4];
#pragma unroll
    for (int i = 0; i < 4; i++) out[i] = (v[i] - mu) * inv;
    *(float4*)(O + o) = *(float4*)out;
    split_store(out[0], out[1], Ohi + o, Olo + o);
    split_store(out[2], out[3], Ohi + o + 2, Olo + o + 2);
}

// ---------------- host ----------------
static float* sym_ptr(const void* sym) { void* p = nullptr; cudaGetSymbolAddress(&p, sym); return (float*)p; }
static __nv_bfloat16* sym_bf(const void* sym) { void* p = nullptr; cudaGetSymbolAddress(&p, sym); return (__nv_bfloat16*)p; }

extern "C" void kernel_launch(void* const* d_in, const int* in_sizes, int n_in,
                              void* d_out, int out_size)
{
    const int*   dec      = (const int*)d_in[0];
    const int*   enc_in   = (const int*)d_in[1];
    const float* enc_out  = (const float*)d_in[2];
    const float* emb      = (const float*)d_in[3];
    const float* Wq_self  = (const float*)d_in[4];
    const float* Wk_self  = (const float*)d_in[5];
    const float* Wv_self  = (const float*)d_in[6];
    const float* Wo_self  = (const float*)d_in[7];
    const float* Wq_cross = (const float*)d_in[8];
    const float* Wk_cross = (const float*)d_in[9];
    const float* Wv_cross = (const float*)d_in[10];
    const float* Wo_cross = (const float*)d_in[11];
    const float* W1       = (const float*)d_in[12];
    const float* W2       = (const float*)d_in[13];

    float* x   = sym_ptr(g_x);
    float* t1  = sym_ptr(g_t);
    __nv_bfloat16* xhi = sym_bf(g_xhi); __nv_bfloat16* xlo = sym_bf(g_xlo);
    __nv_bfloat16* qkvhi = sym_bf(g_qkvhi); __nv_bfloat16* qkvlo = sym_bf(g_qkvlo);
    __nv_bfloat16* chi = sym_bf(g_chi); __nv_bfloat16* clo = sym_bf(g_clo);
    __nv_bfloat16* hhi = sym_bf(g_hhi); __nv_bfloat16* hlo = sym_bf(g_hlo);
    __nv_bfloat16* ehi = sym_bf(g_ehi); __nv_bfloat16* elo = sym_bf(g_elo);
    __nv_bfloat16* wthi = sym_bf(g_wthi); __nv_bfloat16* wtlo = sym_bf(g_wtlo);
    __nv_bfloat16* vthi = sym_bf(g_vthi); __nv_bfloat16* vtlo = sym_bf(g_vtlo);

    cudaFuncSetAttribute(mm2<0>, cudaFuncAttributeMaxDynamicSharedMemorySize, GSMEM);
    cudaFuncSetAttribute(mm2<1>, cudaFuncAttributeMaxDynamicSharedMemorySize, GSMEM);
    cudaFuncSetAttribute(flash<0>, cudaFuncAttributeMaxDynamicSharedMemorySize, FL_SMEM);
    cudaFuncSetAttribute(flash<1>, cudaFuncAttributeMaxDynamicSharedMemorySize, FL_SMEM);

    const int M = Bz * Tt;

    dim3 b32(32, 32);
    const float* projSrc[8] = { Wq_self, Wk_self, Wv_self, Wo_self,
                                Wq_cross, Wk_cross, Wv_cross, Wo_cross };
    for (int mi = 0; mi < 8; mi++)
        wt_build<<<dim3(16, 16, NL), b32>>>(projSrc[mi], wthi + mi * 262144, wtlo + mi * 262144,
                                            Dm, Dm, (long)Dm * Dm, WT_L);
    wt_build<<<dim3(64, 16, NL), b32>>>(W1, wthi + 2097152, wtlo + 2097152, Dm, FFd, (long)Dm * FFd, WT_L);
    wt_build<<<dim3(16, 64, NL), b32>>>(W2, wthi + 3145728, wtlo + 3145728, FFd, Dm, (long)FFd * Dm, WT_L);

    enc_split<<<Bz * Ss, 128>>>(enc_out, ehi, elo);
    embed_k<<<Bz * Tt, 128>>>(dec, emb, x, xhi, xlo);

    dim3 gQKV(1536 / 64, M / 128, 1);
    dim3 gQ(512 / 64, M / 128, 1);
    dim3 gKV(1024 / 64, M / 128, 1);
    dim3 gWo(512 / 64, M / 128, 1);
    dim3 gFF1(FFd / 64, M / 128, 1);
    dim3 gFF2(512 / 64, M / 128, 1);
    dim3 gFl(Tt / 128, Bz * Hh, 1);
    dim3 gVt(Ss / 32, 2, Bz * Hh);

    for (int l = 0; l < NL; l++) {
        long wb = (long)l * WT_L;
        const __nv_bfloat16* Wqkv_h = wthi + wb;            const __nv_bfloat16* Wqkv_l = wtlo + wb;
        const __nv_bfloat16* Wos_h  = wthi + wb + 3*262144; const __nv_bfloat16* Wos_l  = wtlo + wb + 3*262144;
        const __nv_bfloat16* Wqc_h  = wthi + wb + 4*262144; const __nv_bfloat16* Wqc_l  = wtlo + wb + 4*262144;
        const __nv_bfloat16* Wkvc_h = wthi + wb + 5*262144; const __nv_bfloat16* Wkvc_l = wtlo + wb + 5*262144;
        const __nv_bfloat16* Woc_h  = wthi + wb + 7*262144; const __nv_bfloat16* Woc_l  = wtlo + wb + 7*262144;
        const __nv_bfloat16* w1_h = wthi + wb + 2097152;    const __nv_bfloat16* w1_l = wtlo + wb + 2097152;
        const __nv_bfloat16* w2_h = wthi + wb + 3145728;    const __nv_bfloat16* w2_l = wtlo + wb + 3145728;

        // ---- self-attention: fused QKV (N=1536) ----
        mm2<0><<<gQKV, 256, GSMEM>>>(xhi, xlo, Dm, Wqkv_h, Wqkv_l, Dm,
                                     nullptr, qkvhi, qkvlo, 1536, Dm);
        vt_build<<<gVt, b32>>>(qkvhi, qkvlo, vthi, vtlo);
        flash<1><<<gFl, 256, FL_SMEM>>>(qkvhi, qkvlo, 1536, qkvhi + 512, qkvlo + 512,
                                        vthi, vtlo, chi, clo, dec);
        mm2<0><<<gWo, 256, GSMEM>>>(chi, clo, Dm, Wos_h, Wos_l, Dm,
                                    t1, nullptr, nullptr, Dm, Dm);
        add_ln_k<<<M, 128>>>(t1, x, x, xhi, xlo);

        // ---- cross-attention: Q (N=512) + fused KV (N=1024) ----
        mm2<0><<<gQ, 256, GSMEM>>>(xhi, xlo, Dm, Wqc_h, Wqc_l, Dm,
                                   nullptr, qkvhi, qkvlo, 1536, Dm);
        mm2<0><<<gKV, 256, GSMEM>>>(ehi, elo, Dm, Wkvc_h, Wkvc_l, Dm,
                                    nullptr, qkvhi + 512, qkvlo + 512, 1536, Dm);
        vt_build<<<gVt, b32>>>(qkvhi, qkvlo, vthi, vtlo);
        flash<0><<<gFl, 256, FL_SMEM>>>(qkvhi, qkvlo, 1536, qkvhi + 512, qkvlo + 512,
                                        vthi, vtlo, chi, clo, enc_in);
        mm2<0><<<gWo, 256, GSMEM>>>(chi, clo, Dm, Woc_h, Woc_l, Dm,
                                    t1, nullptr, nullptr, Dm, Dm);
        add_ln_k<<<M, 128>>>(t1, x, x, xhi, xlo);

        // ---- FFN ----
        mm2<1><<<gFF1, 256, GSMEM>>>(xhi, xlo, Dm, w1_h, w1_l, Dm,
                                     nullptr, hhi, hlo, FFd, Dm);
        mm2<0><<<gFF2, 256, GSMEM>>>(hhi, hlo, FFd, w2_h, w2_l, FFd,
                                     t1, nullptr, nullptr, Dm, FFd);
        add_ln_k<<<M, 128>>>(t1, x, x, xhi, xlo);
    }

    cudaMemcpyAsync(d_out, x, (size_t)M * Dm * sizeof(float), cudaMemcpyDeviceToDevice);
}

// round 13
// speedup vs baseline: 1.0604x; 1.0604x over previous
#include <cuda_runtime.h>
#include <cuda_bf16.h>
#include <math.h>
#include <stdint.h>

#define Bz 8
#define Tt 1024
#define Ss 1024
#define Dm 512
#define Hh 8
#define DKh 64
#define FFd 2048
#define NL 6

// ---------------- scratch (device globals) ----------------
__device__ __align__(256) float g_x  [Bz*Tt*Dm];
__device__ __align__(256) float g_t  [Bz*Tt*Dm];

__device__ __align__(256) __nv_bfloat16 g_xhi[Bz*Tt*Dm];
__device__ __align__(256) __nv_bfloat16 g_xlo[Bz*Tt*Dm];
__device__ __align__(256) __nv_bfloat16 g_qkvhi[Bz*Tt*1536];
__device__ __align__(256) __nv_bfloat16 g_qkvlo[Bz*Tt*1536];
__device__ __align__(256) __nv_bfloat16 g_chi[Bz*Tt*Dm];
__device__ __align__(256) __nv_bfloat16 g_clo[Bz*Tt*Dm];
__device__ __align__(256) __nv_bfloat16 g_hhi[Bz*Tt*FFd];
__device__ __align__(256) __nv_bfloat16 g_hlo[Bz*Tt*FFd];
__device__ __align__(256) __nv_bfloat16 g_ehi[Bz*Ss*Dm];
__device__ __align__(256) __nv_bfloat16 g_elo[Bz*Ss*Dm];

#define WT_L 4194304
__device__ __align__(256) __nv_bfloat16 g_wthi[(size_t)NL*WT_L];
__device__ __align__(256) __nv_bfloat16 g_wtlo[(size_t)NL*WT_L];
__device__ __align__(256) __nv_bfloat16 g_vthi[Bz*Hh*DKh*Ss];
__device__ __align__(256) __nv_bfloat16 g_vtlo[Bz*Hh*DKh*Ss];

// ---------------- helpers ----------------
__device__ __forceinline__ uint32_t smem_u32(const void* p) {
    uint32_t a;
    asm("{ .reg .u64 t; cvta.to.shared.u64 t, %1; cvt.u32.u64 %0, t; }" : "=r"(a) : "l"(p));
    return a;
}
__device__ __forceinline__ void cpa16(uint32_t s, const void* g) {
    asm volatile("cp.async.ca.shared.global [%0], [%1], 16;" :: "r"(s), "l"(g));
}
#define CP_COMMIT() asm volatile("cp.async.commit_group;" ::: "memory")
#define CP_WAIT1()  asm volatile("cp.async.wait_group 1;" ::: "memory")
#define CP_WAIT0()  asm volatile("cp.async.wait_group 0;" ::: "memory")

__device__ __forceinline__ void ldm4(uint32_t* r, uint32_t addr) {
    asm volatile("ldmatrix.sync.aligned.m8n8.x4.shared.b16 {%0,%1,%2,%3}, [%4];"
        : "=r"(r[0]), "=r"(r[1]), "=r"(r[2]), "=r"(r[3]) : "r"(addr));
}
__device__ __forceinline__ void mma16816(float* c, const uint32_t* a, const uint32_t* b) {
    asm volatile("mma.sync.aligned.m16n8k16.row.col.f32.bf16.bf16.f32 "
        "{%0,%1,%2,%3}, {%4,%5,%6,%7}, {%8,%9}, {%0,%1,%2,%3};"
        : "+f"(c[0]), "+f"(c[1]), "+f"(c[2]), "+f"(c[3])
        : "r"(a[0]), "r"(a[1]), "r"(a[2]), "r"(a[3]), "r"(b[0]), "r"(b[1]));
}
__device__ __forceinline__ void split_store(float a, float b,
                                            __nv_bfloat16* hi, __nv_bfloat16* lo) {
    __nv_bfloat16 ha = __float2bfloat16(a), hb = __float2bfloat16(b);
    __nv_bfloat162 H; H.x = ha; H.y = hb;
    __nv_bfloat162 L;
    L.x = __float2bfloat16(a - __bfloat162float(ha));
    L.y = __float2bfloat16(b - __bfloat162float(hb));
    *(__nv_bfloat162*)hi = H;
    *(__nv_bfloat162*)lo = L;
}
__device__ __forceinline__ void split_pack(float a, float b, uint32_t& H, uint32_t& L) {
    __nv_bfloat16 ha = __float2bfloat16(a), hb = __float2bfloat16(b);
    __nv_bfloat162 Hv; Hv.x = ha; Hv.y = hb;
    __nv_bfloat162 Lv;
    Lv.x = __float2bfloat16(a - __bfloat162float(ha));
    Lv.y = __float2bfloat16(b - __bfloat162float(hb));
    H = *reinterpret_cast<uint32_t*>(&Hv);
    L = *reinterpret_cast<uint32_t*>(&Lv);
}

// ================= pipelined warp-MMA GEMM (bf16x3, TILE 128x128, operand-major) =================
// D[M,N] = A[M,K] * B^T, pre-split hi/lo bf16. EPI: 0 plain, 1 relu.
#define GPITCH 72
#define GSTAGE ((256 + 256) * GPITCH * 2)   // 73728
#define GSMEM  (2 * GSTAGE)                 // 147456

template<int EPI>
__global__ void __launch_bounds__(256) mm2(
    const __nv_bfloat16* __restrict__ Ah, const __nv_bfloat16* __restrict__ Al, int lda,
    const __nv_bfloat16* __restrict__ Bh, const __nv_bfloat16* __restrict__ Bl, int ldb,
    float* __restrict__ Cf, __nv_bfloat16* __restrict__ Chi, __nv_bfloat16* __restrict__ Clo,
    int ldc, int K)
{
    extern __shared__ char smem[];
    uint32_t sb = smem_u32(smem);

    int tid = threadIdx.x, warp = tid >> 5, lane = tid & 31;
    int m0 = blockIdx.y * 128, n0 = blockIdx.x * 128;
    int wm = warp & 1, wn = warp >> 1;            // 2x4 warp grid
    int mbase = wm * 64, nbase = wn * 32;         // warp tile 64x32

    float acc[4][4][4];
#pragma unroll
    for (int i = 0; i < 4; i++)
#pragma unroll
        for (int j = 0; j < 4; j++)
#pragma unroll
            for (int c = 0; c < 4; c++) acc[i][j][c] = 0.0f;

    const int a_row = (lane & 15), a_koff = ((lane >> 4) << 3);
    const int b_row = ((lane >> 4) << 3) + (lane & 7), b_koff = (((lane >> 3) & 1) << 3);

    auto issue = [&](int stage, int k0) {
        uint32_t base = sb + stage * GSTAGE;
        uint32_t uAh = base, uAl = base + 128 * GPITCH * 2;
        uint32_t uBh = base + 256 * GPITCH * 2, uBl = uBh + 128 * GPITCH * 2;
#pragma unroll
        for (int i = 0; i < 4; i++) {
            int idx = tid + 256 * i;
            int r = idx >> 3, c = idx & 7;
            long ga = (long)(m0 + r) * lda + k0 + c * 8;
            long gb = (long)(n0 + r) * ldb + k0 + c * 8;
            uint32_t so = (uint32_t)(r * GPITCH + c * 8) * 2;
            cpa16(uAh + so, Ah + ga);
            cpa16(uAl + so, Al + ga);
            cpa16(uBh + so, Bh + gb);
            cpa16(uBl + so, Bl + gb);
        }
        CP_COMMIT();
    };

    int nch = K >> 6;
    issue(0, 0);
    if (nch > 1) issue(1, 64);

    for (int it = 0; it < nch; it++) {
        if (it + 2 <= nch) CP_WAIT1(); else CP_WAIT0();
        __syncthreads();
        uint32_t base = sb + (it & 1) * GSTAGE;
        uint32_t uAh = base, uAl = base + 128 * GPITCH * 2;
        uint32_t uBh = base + 256 * GPITCH * 2, uBl = uBh + 128 * GPITCH * 2;

#pragma unroll
        for (int ks = 0; ks < 4; ks++) {
            uint32_t ah[4][4], al[4][4];
#pragma unroll
            for (int mi = 0; mi < 4; mi++) {
                uint32_t ro = (uint32_t)((mbase + mi * 16 + a_row) * GPITCH + ks * 16 + a_koff) * 2;
                ldm4(ah[mi], uAh + ro);
                ldm4(al[mi], uAl + ro);
            }
            uint32_t bh[4][2], bl[4][2];
#pragma unroll
            for (int nj = 0; nj < 2; nj++) {
                uint32_t ro = (uint32_t)((nbase + nj * 16 + b_row) * GPITCH + ks * 16 + b_koff) * 2;
                uint32_t t4[4];
                ldm4(t4, uBh + ro);
                bh[2 * nj][0] = t4[0]; bh[2 * nj][1] = t4[1];
                bh[2 * nj + 1][0] = t4[2]; bh[2 * nj + 1][1] = t4[3];
                ldm4(t4, uBl + ro);
                bl[2 * nj][0] = t4[0]; bl[2 * nj][1] = t4[1];
                bl[2 * nj + 1][0] = t4[2]; bl[2 * nj + 1][1] = t4[3];
            }
#pragma unroll
            for (int mi = 0; mi < 4; mi++)
#pragma unroll
                for (int ni = 0; ni < 4; ni++) {
                    mma16816(acc[mi][ni], ah[mi], bh[ni]);
                    mma16816(acc[mi][ni], ah[mi], bl[ni]);
                    mma16816(acc[mi][ni], al[mi], bh[ni]);
                }
        }
        __syncthreads();
        if (it + 2 < nch) issue(it & 1, (it + 2) * 64);
    }

#pragma unroll
    for (int mi = 0; mi < 4; mi++) {
#pragma unroll
        for (int ni = 0; ni < 4; ni++) {
            int m = m0 + mbase + mi * 16 + (lane >> 2);
            int n = n0 + nbase + ni * 8 + (lane & 3) * 2;
            float* c0 = acc[mi][ni];
            float a0 = c0[0], a1 = c0[1], a2 = c0[2], a3 = c0[3];
            if (EPI == 1) {
                a0 = fmaxf(a0, 0.f); a1 = fmaxf(a1, 0.f);
                a2 = fmaxf(a2, 0.f); a3 = fmaxf(a3, 0.f);
            }
            if (Cf) {
                *(float2*)(Cf + (long)m * ldc + n) = make_float2(a0, a1);
                *(float2*)(Cf + (long)(m + 8) * ldc + n) = make_float2(a2, a3);
            }
            if (Chi) {
                split_store(a0, a1, Chi + (long)m * ldc + n, Clo + (long)m * ldc + n);
                split_store(a2, a3, Chi + (long)(m + 8) * ldc + n, Clo + (long)(m + 8) * ldc + n);
            }
        }
    }
}

// ================= fused flash attention (bf16x3, online softmax) =================
#define KPITCH 72
#define VPITCH 136
#define FL_STAGE 71680
#define FL_SMEM  (2 * FL_STAGE + 512)

template<int CAUSAL>
__global__ void __launch_bounds__(256) flash(
    const __nv_bfloat16* __restrict__ Qh, const __nv_bfloat16* __restrict__ Ql, int ldq,
    const __nv_bfloat16* __restrict__ Kh, const __nv_bfloat16* __restrict__ Kl,
    const __nv_bfloat16* __restrict__ Vth, const __nv_bfloat16* __restrict__ Vtl,
    __nv_bfloat16* __restrict__ Chi, __nv_bfloat16* __restrict__ Clo,
    const int* __restrict__ tok)
{
    extern __shared__ char smem[];
    uint32_t sb = smem_u32(smem);
    float* msk = (float*)(smem + 2 * FL_STAGE);

    int tid = threadIdx.x, warp = tid >> 5, lane = tid & 31;
    int z = blockIdx.y, b = z >> 3, h = z & 7;
    int q0 = blockIdx.x * 128;
    int mbase = warp * 16;

    const __nv_bfloat16* Qhb = Qh + ((long)(b * Tt + q0)) * ldq + h * 64;
    const __nv_bfloat16* Qlb = Ql + ((long)(b * Tt + q0)) * ldq + h * 64;
    const __nv_bfloat16* Khb = Kh + ((long)b * Ss) * ldq + h * 64;
    const __nv_bfloat16* Klb = Kl + ((long)b * Ss) * ldq + h * 64;
    const __nv_bfloat16* Vhb = Vth + (long)z * 64 * Ss;
    const __nv_bfloat16* Vlb = Vtl + (long)z * 64 * Ss;
    const int* tokb = tok + b * 1024;

    const int a_row = (lane & 15), a_koff = ((lane >> 4) << 3);
    const int b_row = ((lane >> 4) << 3) + (lane & 7), b_koff = (((lane >> 3) & 1) << 3);

    {
        uint32_t uQh = sb, uQl = sb + 128 * KPITCH * 2;
#pragma unroll
        for (int i = 0; i < 4; i++) {
            int idx = tid + 256 * i;
            int r = idx >> 3, c = idx & 7;
            long g = (long)r * ldq + c * 8;
            uint32_t so = (uint32_t)(r * KPITCH + c * 8) * 2;
            cpa16(uQh + so, Qhb + g);
            cpa16(uQl + so, Qlb + g);
        }
        CP_COMMIT(); CP_WAIT0();
        __syncthreads();
    }
    uint32_t qh[4][4], ql[4][4];
#pragma unroll
    for (int ks = 0; ks < 4; ks++) {
        ldm4(qh[ks], sb + (uint32_t)((mbase + a_row) * KPITCH + ks * 16 + a_koff) * 2);
        ldm4(ql[ks], sb + 128 * KPITCH * 2 + (uint32_t)((mbase + a_row) * KPITCH + ks * 16 + a_koff) * 2);
    }
    __syncthreads();

    auto issue = [&](int stage, int kb) {
        uint32_t base = sb + stage * FL_STAGE;
        uint32_t uKhi = base, uKlo = base + 18432;
        uint32_t uVhi = base + 36864, uVlo = base + 54272;
#pragma unroll
        for (int i = 0; i < 4; i++) {
            int idx = tid + 256 * i;
            int r = idx >> 3, c = idx & 7;
            long g = (long)(kb * 128 + r) * ldq + c * 8;
            uint32_t so = (uint32_t)(r * KPITCH + c * 8) * 2;
            cpa16(uKhi + so, Khb + g);
            cpa16(uKlo + so, Klb + g);
        }
#pragma unroll
        for (int i = 0; i < 4; i++) {
            int idx = tid + 256 * i;
            int r = idx >> 4, c = idx & 15;
            long g = (long)r * Ss + kb * 128 + c * 8;
            uint32_t so = (uint32_t)(r * VPITCH + c * 8) * 2;
            cpa16(uVhi + so, Vhb + g);
            cpa16(uVlo + so, Vlb + g);
        }
        CP_COMMIT();
    };

    const float CSC = 0.125f * 1.4426950408889634f;
    float oacc[8][4];
#pragma unroll
    for (int i = 0; i < 8; i++)
#pragma unroll
        for (int c = 0; c < 4; c++) oacc[i][c] = 0.0f;
    float m0 = -INFINITY, m1 = -INFINITY, l0 = 0.0f, l1 = 0.0f;
    const int qr0 = q0 + mbase + (lane >> 2);
    const int qr1 = qr0 + 8;

    int nkb = CAUSAL ? (q0 / 128 + 1) : (Ss / 128);
    issue(0, 0);
    if (nkb > 1) issue(1, 1);

    for (int kb = 0; kb < nkb; kb++) {
        int tokv = 0;
        if (tid < 128) tokv = tokb[kb * 128 + tid];
        if (kb + 2 <= nkb) CP_WAIT1(); else CP_WAIT0();
        __syncthreads();
        if (tid < 128) msk[tid] = (tokv == 0) ? 1.0f : 0.0f;
        __syncthreads();

        uint32_t base = sb + (kb & 1) * FL_STAGE;
        uint32_t uK[2] = { base, base + 18432 };
        uint32_t uV[2] = { base + 36864, base + 54272 };

        float sacc[16][4];
#pragma unroll
        for (int i = 0; i < 16; i++)
#pragma unroll
            for (int c = 0; c < 4; c++) sacc[i][c] = 0.0f;
#pragma unroll
        for (int pass = 0; pass < 3; pass++) {
            uint32_t (*qr)[4] = (pass == 2) ? ql : qh;
            uint32_t pK = uK[pass == 1];
#pragma unroll
            for (int ks = 0; ks < 4; ks++) {
#pragma unroll
                for (int nj = 0; nj < 8; nj++) {
                    uint32_t t4[4];
                    ldm4(t4, pK + (uint32_t)((nj * 16 + b_row) * KPITCH + ks * 16 + b_koff) * 2);
                    mma16816(sacc[2 * nj], qr[ks], t4);
                    mma16816(sacc[2 * nj + 1], qr[ks], t4 + 2);
                }
            }
        }

        float mx0 = -INFINITY, mx1 = -INFINITY;
#pragma unroll
        for (int t = 0; t < 16; t++) {
            int cb = t * 8 + (lane & 3) * 2;
            float2 mv = *(float2*)(msk + cb);
            int kg = kb * 128 + cb;
            bool M0 = (mv.x != 0.0f), M1 = (mv.y != 0.0f);
            bool c00 = M0 || (CAUSAL && kg > qr0);
            bool c01 = M1 || (CAUSAL && kg + 1 > qr0);
            bool c10 = M0 || (CAUSAL && kg > qr1);
            bool c11 = M1 || (CAUSAL && kg + 1 > qr1);
            sacc[t][0] = c00 ? -1e9f : sacc[t][0] * CSC;
            sacc[t][1] = c01 ? -1e9f : sacc[t][1] * CSC;
            sacc[t][2] = c10 ? -1e9f : sacc[t][2] * CSC;
            sacc[t][3] = c11 ? -1e9f : sacc[t][3] * CSC;
            mx0 = fmaxf(mx0, fmaxf(sacc[t][0], sacc[t][1]));
            mx1 = fmaxf(mx1, fmaxf(sacc[t][2], sacc[t][3]));
        }
        mx0 = fmaxf(mx0, __shfl_xor_sync(0xffffffffu, mx0, 1));
        mx0 = fmaxf(mx0, __shfl_xor_sync(0xffffffffu, mx0, 2));
        mx1 = fmaxf(mx1, __shfl_xor_sync(0xffffffffu, mx1, 1));
        mx1 = fmaxf(mx1, __shfl_xor_sync(0xffffffffu, mx1, 2));

        float m0n = fmaxf(m0, mx0), m1n = fmaxf(m1, mx1);
        float al0 = exp2f(m0 - m0n), al1 = exp2f(m1 - m1n);
        m0 = m0n; m1 = m1n;
        l0 *= al0; l1 *= al1;
#pragma unroll
        for (int i = 0; i < 8; i++) {
            oacc[i][0] *= al0; oacc[i][1] *= al0;
            oacc[i][2] *= al1; oacc[i][3] *= al1;
        }

        float ls0 = 0.0f, ls1 = 0.0f;
#pragma unroll
        for (int half = 0; half < 2; half++) {
            uint32_t ph[4][4], pl[4][4];
#pragma unroll
            for (int ksv = 0; ksv < 4; ksv++) {
                int tA = half * 8 + ksv * 2, tB = tA + 1;
                float p00 = exp2f(sacc[tA][0] - m0), p01 = exp2f(sacc[tA][1] - m0);
                float p02 = exp2f(sacc[tA][2] - m1), p03 = exp2f(sacc[tA][3] - m1);
                float p10 = exp2f(sacc[tB][0] - m0), p11 = exp2f(sacc[tB][1] - m0);
                float p12 = exp2f(sacc[tB][2] - m1), p13 = exp2f(sacc[tB][3] - m1);
                ls0 += p00 + p01 + p10 + p11;
                ls1 += p02 + p03 + p12 + p13;
                split_pack(p00, p01, ph[ksv][0], pl[ksv][0]);
                split_pack(p02, p03, ph[ksv][1], pl[ksv][1]);
                split_pack(p10, p11, ph[ksv][2], pl[ksv][2]);
                split_pack(p12, p13, ph[ksv][3], pl[ksv][3]);
            }
#pragma unroll
            for (int pass = 0; pass < 3; pass++) {
                uint32_t (*pa)[4] = (pass == 2) ? pl : ph;
                uint32_t pV = uV[pass == 1];
#pragma unroll
                for (int ksv = 0; ksv < 4; ksv++) {
                    int ksg = half * 4 + ksv;
#pragma unroll
                    for (int nj = 0; nj < 4; nj++) {
                        uint32_t t4[4];
                        ldm4(t4, pV + (uint32_t)((nj * 16 + b_row) * VPITCH + ksg * 16 + b_koff) * 2);
                        mma16816(oacc[2 * nj], pa[ksv], t4);
                        mma16816(oacc[2 * nj + 1], pa[ksv], t4 + 2);
                    }
                }
            }
        }
        ls0 += __shfl_xor_sync(0xffffffffu, ls0, 1);
        ls0 += __shfl_xor_sync(0xffffffffu, ls0, 2);
        ls1 += __shfl_xor_sync(0xffffffffu, ls1, 1);
        ls1 += __shfl_xor_sync(0xffffffffu, ls1, 2);
        l0 += ls0; l1 += ls1;

        __syncthreads();
        if (kb + 2 < nkb) issue(kb & 1, kb + 2);
    }

    float il0 = 1.0f / l0, il1 = 1.0f / l1;
    long gr0 = (long)(b * Tt + q0 + mbase + (lane >> 2));
    long gr1 = gr0 + 8;
#pragma unroll
    for (int oi = 0; oi < 8; oi++) {
        int col = h * 64 + oi * 8 + (lane & 3) * 2;
        split_store(oacc[oi][0] * il0, oacc[oi][1] * il0,
                    Chi + gr0 * Dm + col, Clo + gr0 * Dm + col);
        split_store(oacc[oi][2] * il1, oacc[oi][3] * il1,
                    Chi + gr1 * Dm + col, Clo + gr1 * Dm + col);
    }
}

// ---------------- weight transpose + split ----------------
struct P8 { const float* p[8]; };

// all 8 projection mats (512x512), all layers, one launch: grid.z = 8*NL
__global__ void wt_build8(P8 srcs, __nv_bfloat16* __restrict__ Whi,
                          __nv_bfloat16* __restrict__ Wlo)
{
    int z = blockIdx.z;
    int l = z >> 3, mi = z & 7;
    const float* W = srcs.p[mi] + (long)l * Dm * Dm;
    __nv_bfloat16* dh = Whi + (long)l * WT_L + mi * 262144;
    __nv_bfloat16* dl = Wlo + (long)l * WT_L + mi * 262144;
    __shared__ float t[32][33];
    int k0 = blockIdx.y * 32, n0 = blockIdx.x * 32;
    t[threadIdx.y][threadIdx.x] = W[(long)(k0 + threadIdx.y) * Dm + n0 + threadIdx.x];
    __syncthreads();
    float v = t[threadIdx.x][threadIdx.y];
    long o = (long)(n0 + threadIdx.y) * Dm + k0 + threadIdx.x;
    __nv_bfloat16 h = __float2bfloat16(v);
    dh[o] = h;
    dl[o] = __float2bfloat16(v - __bfloat162float(h));
}

__global__ void wt_build(const float* __restrict__ W, __nv_bfloat16* __restrict__ Whi,
                         __nv_bfloat16* __restrict__ Wlo, int Kd, int Nd,
                         long srcStride, long dstStride)
{
    int l = blockIdx.z;
    W += (long)l * srcStride; Whi += (long)l * dstStride; Wlo += (long)l * dstStride;
    __shared__ float t[32][33];
    int k0 = blockIdx.y * 32, n0 = blockIdx.x * 32;
    t[threadIdx.y][threadIdx.x] = W[(long)(k0 + threadIdx.y) * Nd + n0 + threadIdx.x];
    __syncthreads();
    float v = t[threadIdx.x][threadIdx.y];
    long o = (long)(n0 + threadIdx.y) * Kd + k0 + threadIdx.x;
    __nv_bfloat16 h = __float2bfloat16(v);
    Whi[o] = h;
    Wlo[o] = __float2bfloat16(v - __bfloat162float(h));
}

// ---------------- V transpose from split qkv buffer ----------------
__global__ void vt_build(const __nv_bfloat16* __restrict__ qh, const __nv_bfloat16* __restrict__ qlo,
                         __nv_bfloat16* __restrict__ vhi, __nv_bfloat16* __restrict__ vlo)
{
    int z = blockIdx.z, b = z >> 3, h = z & 7;
    __shared__ __nv_bfloat16 th[32][34], tl[32][34];
    int s0 = blockIdx.x * 32, d0 = blockIdx.y * 32;
    long src = (long)(b * Ss + s0 + threadIdx.y) * 1536 + 1024 + h * 64 + d0 + threadIdx.x;
    th[threadIdx.y][threadIdx.x] = qh[src];
    tl[threadIdx.y][threadIdx.x] = qlo[src];
    __syncthreads();
    long o = (long)(z * 64 + d0 + threadIdx.y) * Ss + s0 + threadIdx.x;
    vhi[o] = th[threadIdx.x][threadIdx.y];
    vlo[o] = tl[threadIdx.x][threadIdx.y];
}

// ---------------- embedding + PE ----------------
__global__ void embed_k(const int* __restrict__ dec, const float* __restrict__ emb,
                        float* __restrict__ x, __nv_bfloat16* __restrict__ xhi,
                        __nv_bfloat16* __restrict__ xlo)
{
    int bt = blockIdx.x;
    int tpos = bt & (Tt - 1);
    int tokv = dec[bt];
    int d0 = threadIdx.x * 4;
    const double c0 = -9.210340371976184 / (double)Dm;
    float vals[4];
#pragma unroll
    for (int i = 0; i < 4; i++) {
        int d = d0 + i;
        int pair = d >> 1;
        double div = exp((double)(2 * pair) * c0);
        double ang = (double)tpos * div;
        float pe = (float)((d & 1) ? cos(ang) : sin(ang));
        float e = (tokv == 0) ? 0.0f : emb[(size_t)tokv * Dm + d];
        vals[i] = e + pe;
    }
    size_t o = (size_t)bt * Dm + d0;
    *(float4*)(x + o) = *(float4*)vals;
    split_store(vals[0], vals[1], xhi + o, xlo + o);
    split_store(vals[2], vals[3], xhi + o + 2, xlo + o + 2);
}

// ---------------- enc_out split ----------------
__global__ void enc_split(const float* __restrict__ e, __nv_bfloat16* __restrict__ ehi,
                          __nv_bfloat16* __restrict__ elo)
{
    size_t o = (size_t)blockIdx.x * Dm + threadIdx.x * 4;
    float4 v = *(const float4*)(e + o);
    split_store(v.x, v.y, ehi + o, elo + o);
    split_store(v.z, v.w, ehi + o + 2, elo + o + 2);
}

// ---------------- out = LayerNorm(a + b) ----------------
__global__ void add_ln_k(const float* __restrict__ A, const float* __restrict__ Bres,
                         float* __restrict__ O, __nv_bfloat16* __restrict__ Ohi,
                         __nv_bfloat16* __restrict__ Olo)
{
    size_t r = blockIdx.x;
    int t = threadIdx.x;
    size_t o = r * Dm + t * 4;
    float4 va = *(const float4*)(A + o);
    float4 vb = *(const float4*)(Bres + o);
    float v[4] = { va.x + vb.x, va.y + vb.y, va.z + vb.z, va.w + vb.w };
    float s = v[0] + v[1] + v[2] + v[3];
    __shared__ float red[128];
    red[t] = s; __syncthreads();
    for (int st = 64; st > 0; st >>= 1) { if (t < st) red[t] += red[t + st]; __syncthreads(); }
    float mu = red[0] * (1.0f / Dm);
    __syncthreads();
    float s2 = 0.0f;
#pragma unroll
    for (int i = 0; i < 4; i++) { float d = v[i] - mu; s2 += d * d; }
    red[t] = s2; __syncthreads();
    for (int st = 64; st > 0; st >>= 1) { if (t < st) red[t] += red[t + st]; __syncthreads(); }
    float inv = rsqrtf(red[0] * (1.0f / Dm) + 1e-5f);
    float out[4];
#pragma unroll
    for (int i = 0; i < 4; i++) out[i] = (v[i] - mu) * inv;
    *(float4*)(O + o) = *(float4*)out;
    split_store(out[0], out[1], Ohi + o, Olo + o);
    split_store(out[2], out[3], Ohi + o + 2, Olo + o + 2);
}

// ---------------- host ----------------
static float* sym_ptr(const void* sym) { void* p = nullptr; cudaGetSymbolAddress(&p, sym); return (float*)p; }
static __nv_bfloat16* sym_bf(const void* sym) { void* p = nullptr; cudaGetSymbolAddress(&p, sym); return (__nv_bfloat16*)p; }

extern "C" void kernel_launch(void* const* d_in, const int* in_sizes, int n_in,
                              void* d_out, int out_size)
{
    const int*   dec      = (const int*)d_in[0];
    const int*   enc_in   = (const int*)d_in[1];
    const float* enc_out  = (const float*)d_in[2];
    const float* emb      = (const float*)d_in[3];
    const float* Wq_self  = (const float*)d_in[4];
    const float* Wk_self  = (const float*)d_in[5];
    const float* Wv_self  = (const float*)d_in[6];
    const float* Wo_self  = (const float*)d_in[7];
    const float* Wq_cross = (const float*)d_in[8];
    const float* Wk_cross = (const float*)d_in[9];
    const float* Wv_cross = (const float*)d_in[10];
    const float* Wo_cross = (const float*)d_in[11];
    const float* W1       = (const float*)d_in[12];
    const float* W2       = (const float*)d_in[13];

    float* x   = sym_ptr(g_x);
    float* t1  = sym_ptr(g_t);
    __nv_bfloat16* xhi = sym_bf(g_xhi); __nv_bfloat16* xlo = sym_bf(g_xlo);
    __nv_bfloat16* qkvhi = sym_bf(g_qkvhi); __nv_bfloat16* qkvlo = sym_bf(g_qkvlo);
    __nv_bfloat16* chi = sym_bf(g_chi); __nv_bfloat16* clo = sym_bf(g_clo);
    __nv_bfloat16* hhi = sym_bf(g_hhi); __nv_bfloat16* hlo = sym_bf(g_hlo);
    __nv_bfloat16* ehi = sym_bf(g_ehi); __nv_bfloat16* elo = sym_bf(g_elo);
    __nv_bfloat16* wthi = sym_bf(g_wthi); __nv_bfloat16* wtlo = sym_bf(g_wtlo);
    __nv_bfloat16* vthi = sym_bf(g_vthi); __nv_bfloat16* vtlo = sym_bf(g_vtlo);

    cudaFuncSetAttribute(mm2<0>, cudaFuncAttributeMaxDynamicSharedMemorySize, GSMEM);
    cudaFuncSetAttribute(mm2<1>, cudaFuncAttributeMaxDynamicSharedMemorySize, GSMEM);
    cudaFuncSetAttribute(flash<0>, cudaFuncAttributeMaxDynamicSharedMemorySize, FL_SMEM);
    cudaFuncSetAttribute(flash<1>, cudaFuncAttributeMaxDynamicSharedMemorySize, FL_SMEM);

    const int M = Bz * Tt;

    // ---- setup: 3 wt_build launches + enc_split + embed, so launch #6 = mm2 (ncu -s 5 -c 1) ----
    dim3 b32(32, 32);
    P8 srcs;
    srcs.p[0] = Wq_self;  srcs.p[1] = Wk_self;  srcs.p[2] = Wv_self;  srcs.p[3] = Wo_self;
    srcs.p[4] = Wq_cross; srcs.p[5] = Wk_cross; srcs.p[6] = Wv_cross; srcs.p[7] = Wo_cross;
    wt_build8<<<dim3(16, 16, 8 * NL), b32>>>(srcs, wthi, wtlo);
    wt_build<<<dim3(64, 16, NL), b32>>>(W1, wthi + 2097152, wtlo + 2097152, Dm, FFd, (long)Dm * FFd, WT_L);
    wt_build<<<dim3(16, 64, NL), b32>>>(W2, wthi + 3145728, wtlo + 3145728, FFd, Dm, (long)FFd * Dm, WT_L);
    enc_split<<<Bz * Ss, 128>>>(enc_out, ehi, elo);
    embed_k<<<Bz * Tt, 128>>>(dec, emb, x, xhi, xlo);

    dim3 gQKV(1536 / 128, M / 128, 1);
    dim3 gQ(512 / 128, M / 128, 1);
    dim3 gKV(1024 / 128, M / 128, 1);
    dim3 gWo(512 / 128, M / 128, 1);
    dim3 gFF1(FFd / 128, M / 128, 1);
    dim3 gFF2(512 / 128, M / 128, 1);
    dim3 gFl(Tt / 128, Bz * Hh, 1);
    dim3 gVt(Ss / 32, 2, Bz * Hh);

    for (int l = 0; l < NL; l++) {
        long wb = (long)l * WT_L;
        const __nv_bfloat16* Wqkv_h = wthi + wb;            const __nv_bfloat16* Wqkv_l = wtlo + wb;
        const __nv_bfloat16* Wos_h  = wthi + wb + 3*262144; const __nv_bfloat16* Wos_l  = wtlo + wb + 3*262144;
        const __nv_bfloat16* Wqc_h  = wthi + wb + 4*262144; const __nv_bfloat16* Wqc_l  = wtlo + wb + 4*262144;
        const __nv_bfloat16* Wkvc_h = wthi + wb + 5*262144; const __nv_bfloat16* Wkvc_l = wtlo + wb + 5*262144;
        const __nv_bfloat16* Woc_h  = wthi + wb + 7*262144; const __nv_bfloat16* Woc_l  = wtlo + wb + 7*262144;
        const __nv_bfloat16* w1_h = wthi + wb + 2097152;    const __nv_bfloat16* w1_l = wtlo + wb + 2097152;
        const __nv_bfloat16* w2_h = wthi + wb + 3145728;    const __nv_bfloat16* w2_l = wtlo + wb + 3145728;

        // ---- self-attention: fused QKV (N=1536) ----
        mm2<0><<<gQKV, 256, GSMEM>>>(xhi, xlo, Dm, Wqkv_h, Wqkv_l, Dm,
                                     nullptr, qkvhi, qkvlo, 1536, Dm);
        vt_build<<<gVt, b32>>>(qkvhi, qkvlo, vthi, vtlo);
        flash<1><<<gFl, 256, FL_SMEM>>>(qkvhi, qkvlo, 1536, qkvhi + 512, qkvlo + 512,
                                        vthi, vtlo, chi, clo, dec);
        mm2<0><<<gWo, 256, GSMEM>>>(chi, clo, Dm, Wos_h, Wos_l, Dm,
                                    t1, nullptr, nullptr, Dm, Dm);
        add_ln_k<<<M, 128>>>(t1, x, x, xhi, xlo);

        // ---- cross-attention: Q (N=512) + fused KV (N=1024) ----
        mm2<0><<<gQ, 256, GSMEM>>>(xhi, xlo, Dm, Wqc_h, Wqc_l, Dm,
                                   nullptr, qkvhi, qkvlo, 1536, Dm);
        mm2<0><<<gKV, 256, GSMEM>>>(ehi, elo, Dm, Wkvc_h, Wkvc_l, Dm,
                                    nullptr, qkvhi + 512, qkvlo + 512, 1536, Dm);
        vt_build<<<gVt, b32>>>(qkvhi, qkvlo, vthi, vtlo);
        flash<0><<<gFl, 256, FL_SMEM>>>(qkvhi, qkvlo, 1536, qkvhi + 512, qkvlo + 512,
                                        vthi, vtlo, chi, clo, enc_in);
        mm2<0><<<gWo, 256, GSMEM>>>(chi, clo, Dm, Woc_h, Woc_l, Dm,
                                    t1, nullptr, nullptr, Dm, Dm);
        add_ln_k<<<M, 128>>>(t1, x, x, xhi, xlo);

        // ---- FFN ----
        mm2<1><<<gFF1, 256, GSMEM>>>(xhi, xlo, Dm, w1_h, w1_l, Dm,
                                     nullptr, hhi, hlo, FFd, Dm);
        mm2<0><<<gFF2, 256, GSMEM>>>(hhi, hlo, FFd, w2_h, w2_l, FFd,
                                     t1, nullptr, nullptr, Dm, FFd);
        add_ln_k<<<M, 128>>>(t1, x, x, xhi, xlo);
    }

    cudaMemcpyAsync(d_out, x, (size_t)M * Dm * sizeof(float), cudaMemcpyDeviceToDevice);
}